// round 7
// baseline (speedup 1.0000x reference)
#include <cuda_runtime.h>
#include <cuda.h>
#include <cstdint>

// CapsuleLayer dynamic routing — TMA (SW128) double-buffered w staging,
// dup-free LDS: each w element is read from SMEM exactly once.
// x: [B=256, N=1152, CI=8] f32, w: [C=10, N=1152, CI=8, CO=16] f32
// out: [C, B, 1, 1, 16] f32
//
// One CTA = (c, pair of b). 576 threads; oq = tid&3 (CO quarter),
// rw = tid>>2 (row 0..143). Each thread reads its row's CO-quarter
// (8 LDS.128 per 144-row block) and accumulates priors for BOTH b's:
// P[8][2][4] (64 regs) stays register-resident through all 3 routing
// iterations.

#define Cc 10
#define Bb 256
#define Nn 1152
#define NTHREADS 576
#define NWARPS 18
#define NBLKS 8
#define RPB 144
#define COLW  18432              // bytes per 128B-column box (144*128)
#define BUFB  (4*COLW)           // 73728 bytes per buffer
#define MBAR_OFF (2*BUFB)
#define WRED_OFF (MBAR_OFF + 16)
#define SRED_OFF (WRED_OFF + NWARPS*2*16*4)
#define OUTV_OFF (SRED_OFF + NWARPS*2*4)
#define SMEM_BYTES (OUTV_OFF + 2*16*4)

__device__ __forceinline__ void mbar_init(uint32_t a, uint32_t cnt) {
    asm volatile("mbarrier.init.shared.b64 [%0], %1;" :: "r"(a), "r"(cnt) : "memory");
}
__device__ __forceinline__ void mbar_expect_tx(uint32_t a, uint32_t bytes) {
    asm volatile("mbarrier.arrive.expect_tx.shared.b64 _, [%0], %1;"
                 :: "r"(a), "r"(bytes) : "memory");
}
__device__ __forceinline__ void mbar_wait(uint32_t a, uint32_t parity) {
    asm volatile(
        "{\n\t.reg .pred P1;\n\t"
        "W_%=:\n\t"
        "mbarrier.try_wait.parity.acquire.cta.shared::cta.b64 P1, [%0], %1, 0x989680;\n\t"
        "@P1 bra.uni D_%=;\n\t"
        "bra.uni W_%=;\n\t"
        "D_%=:\n\t}"
        :: "r"(a), "r"(parity) : "memory");
}
__device__ __forceinline__ void tma2d(uint32_t dst, const CUtensorMap* m,
                                      int cx, int cy, uint32_t mb) {
    asm volatile(
        "cp.async.bulk.tensor.2d.shared::cta.global.tile.mbarrier::complete_tx::bytes "
        "[%0], [%1, {%2, %3}], [%4];"
        :: "r"(dst), "l"(m), "r"(cx), "r"(cy), "r"(mb) : "memory");
}

__global__ __launch_bounds__(NTHREADS, 1)
void capsule_kernel(const __grid_constant__ CUtensorMap tmap,
                    const float* __restrict__ x,
                    float* __restrict__ out)
{
    extern __shared__ char smc[];
    float* wred = (float*)(smc + WRED_OFF);    // [18][2][16]
    float* sred = (float*)(smc + SRED_OFF);    // [18][2]
    float* outv = (float*)(smc + OUTV_OFF);    // [2][16]

    const int tid  = threadIdx.x;
    const int oq   = tid & 3;               // CO quarter
    const int rw   = tid >> 2;              // row within block, 0..143
    const int lane = tid & 31;
    const int wid  = tid >> 5;
    const int c    = blockIdx.x >> 7;
    const int bbase = (blockIdx.x & 127) << 1;

    const uint32_t sbase = (uint32_t)__cvta_generic_to_shared(smc);
    const uint32_t mbar[2] = { sbase + MBAR_OFF, sbase + MBAR_OFF + 8 };

    auto stage = [&](int s) {                 // tid 0 only
        const uint32_t dstb = sbase + (s & 1) * BUFB;
        const int cy = c * Nn + s * RPB;
        mbar_expect_tx(mbar[s & 1], BUFB);
        #pragma unroll
        for (int j = 0; j < 4; ++j)
            tma2d(dstb + j * COLW, &tmap, j * 32, cy, mbar[s & 1]);
    };

    if (tid == 0) { mbar_init(mbar[0], 1); mbar_init(mbar[1], 1); }
    __syncthreads();
    if (tid == 0) { stage(0); stage(1); }

    // ================= Phase 1: priors -> registers =================
    // P[block][g][o-quarter]
    float P[NBLKS][2][4];
    const int r7 = rw & 7;
    const uint32_t rowoff = (uint32_t)rw * 128;

    #pragma unroll
    for (int s = 0; s < NBLKS; ++s) {
        mbar_wait(mbar[s & 1], (s >> 1) & 1);   // block s resident

        const int n = s * RPB + rw;
        const float* xp0 = x + ((size_t)(bbase + 0) * Nn + n) * 8;
        const float* xp1 = x + ((size_t)(bbase + 1) * Nn + n) * 8;
        const float4 xa0 = *(const float4*)xp0;
        const float4 xb0 = *(const float4*)(xp0 + 4);
        const float4 xa1 = *(const float4*)xp1;
        const float4 xb1 = *(const float4*)(xp1 + 4);
        const float xv0[8] = {xa0.x, xa0.y, xa0.z, xa0.w, xb0.x, xb0.y, xb0.z, xb0.w};
        const float xv1[8] = {xa1.x, xa1.y, xa1.z, xa1.w, xb1.x, xb1.y, xb1.z, xb1.w};

        #pragma unroll
        for (int g = 0; g < 2; ++g)
            #pragma unroll
            for (int o = 0; o < 4; ++o) P[s][g][o] = 0.f;

        const char* bufp = smc + (size_t)((s & 1) * BUFB) + rowoff;
        #pragma unroll
        for (int i = 0; i < 8; ++i) {
            // 16B unit C = i*4 + oq; box = i>>1; u = (i&1)*4 + oq
            const uint32_t u = (uint32_t)(((i & 1) * 4) + oq);
            const uint32_t off = (uint32_t)((i >> 1) * COLW)
                               + ((u ^ (uint32_t)r7) << 4);
            const float4 wv = *(const float4*)(bufp + off);
            const float a = xv0[i], b2 = xv1[i];
            P[s][0][0] = fmaf(a,  wv.x, P[s][0][0]);
            P[s][0][1] = fmaf(a,  wv.y, P[s][0][1]);
            P[s][0][2] = fmaf(a,  wv.z, P[s][0][2]);
            P[s][0][3] = fmaf(a,  wv.w, P[s][0][3]);
            P[s][1][0] = fmaf(b2, wv.x, P[s][1][0]);
            P[s][1][1] = fmaf(b2, wv.y, P[s][1][1]);
            P[s][1][2] = fmaf(b2, wv.z, P[s][1][2]);
            P[s][1][3] = fmaf(b2, wv.w, P[s][1][3]);
        }

        __syncthreads();                      // all done reading buf[s&1]
        if (s + 2 < NBLKS && tid == 0) stage(s + 2);
    }

    // ================= Phase 2: routing =================
    // Lane layout: oq = lane&3, row = lane>>2 (8 rows per warp).
    // Quarter join: shfl_xor 1,2. Row reduce: shfl_xor 4,8,16.
    float Lr[NBLKS][2];

    // ---- iteration 0: s = mean_n priors ----
    {
        float acc[2][4];
        #pragma unroll
        for (int g = 0; g < 2; ++g)
            #pragma unroll
            for (int o = 0; o < 4; ++o) {
                float a = 0.f;
                #pragma unroll
                for (int k = 0; k < NBLKS; ++k) a += P[k][g][o];
                acc[g][o] = a;
            }
        #pragma unroll
        for (int off = 4; off <= 16; off <<= 1)
            #pragma unroll
            for (int g = 0; g < 2; ++g)
                #pragma unroll
                for (int o = 0; o < 4; ++o)
                    acc[g][o] += __shfl_xor_sync(0xffffffffu, acc[g][o], off);
        if (lane < 4) {
            #pragma unroll
            for (int g = 0; g < 2; ++g)
                #pragma unroll
                for (int o = 0; o < 4; ++o)
                    wred[wid * 32 + g * 16 + oq * 4 + o] = acc[g][o];
        }
        __syncthreads();
        if (tid < 32) {
            const int g2 = tid & 1, o2 = tid >> 1;
            float sv = 0.f;
            #pragma unroll
            for (int wi = 0; wi < NWARPS; ++wi)
                sv += wred[wi * 32 + g2 * 16 + o2];
            sv *= (1.0f / Nn);
            float sq = sv * sv;
            #pragma unroll
            for (int off = 2; off <= 16; off <<= 1)
                sq += __shfl_xor_sync(0xffffffffu, sq, off);
            const float coef = sq / (1.f + sq) * rsqrtf(sq);
            outv[g2 * 16 + o2] = sv * coef;
        }
        __syncthreads();
    }

    // ---- iterations 1 and 2 ----
    #pragma unroll
    for (int it = 1; it < 3; ++it) {
        float ovr[2][4];
        #pragma unroll
        for (int g = 0; g < 2; ++g)
            #pragma unroll
            for (int o = 0; o < 4; ++o)
                ovr[g][o] = outv[g * 16 + oq * 4 + o];

        // logits + max (quarter-dot, join via shfl 1,2)
        float lmax[2] = {-1e30f, -1e30f};
        #pragma unroll
        for (int k = 0; k < NBLKS; ++k) {
            #pragma unroll
            for (int g = 0; g < 2; ++g) {
                float dot = 0.f;
                #pragma unroll
                for (int o = 0; o < 4; ++o) dot = fmaf(P[k][g][o], ovr[g][o], dot);
                dot += __shfl_xor_sync(0xffffffffu, dot, 1);
                dot += __shfl_xor_sync(0xffffffffu, dot, 2);
                const float L = (it == 1) ? dot : (Lr[k][g] + dot);
                Lr[k][g] = L;
                lmax[g] = fmaxf(lmax[g], L);
            }
        }
        #pragma unroll
        for (int off = 4; off <= 16; off <<= 1)
            #pragma unroll
            for (int g = 0; g < 2; ++g)
                lmax[g] = fmaxf(lmax[g], __shfl_xor_sync(0xffffffffu, lmax[g], off));
        __syncthreads();                 // previous sred consumers done
        if (lane == 0) {
            sred[wid * 2 + 0] = lmax[0];
            sred[wid * 2 + 1] = lmax[1];
        }
        __syncthreads();
        float M[2] = {-1e30f, -1e30f};
        #pragma unroll
        for (int wi = 0; wi < NWARPS; ++wi) {
            M[0] = fmaxf(M[0], sred[wi * 2 + 0]);
            M[1] = fmaxf(M[1], sred[wi * 2 + 1]);
        }

        // exp + Z + weighted sum (single pass, e transient)
        float lsum[2] = {0.f, 0.f};
        float acc[2][4] = {{0.f,0.f,0.f,0.f},{0.f,0.f,0.f,0.f}};
        #pragma unroll
        for (int k = 0; k < NBLKS; ++k) {
            #pragma unroll
            for (int g = 0; g < 2; ++g) {
                const float e = __expf(Lr[k][g] - M[g]);
                lsum[g] += e;
                #pragma unroll
                for (int o = 0; o < 4; ++o)
                    acc[g][o] = fmaf(e, P[k][g][o], acc[g][o]);
            }
        }
        #pragma unroll
        for (int off = 4; off <= 16; off <<= 1)
            #pragma unroll
            for (int g = 0; g < 2; ++g) {
                lsum[g] += __shfl_xor_sync(0xffffffffu, lsum[g], off);
                #pragma unroll
                for (int o = 0; o < 4; ++o)
                    acc[g][o] += __shfl_xor_sync(0xffffffffu, acc[g][o], off);
            }
        __syncthreads();                 // all M reads done
        if (lane == 0) {
            sred[wid * 2 + 0] = lsum[0];
            sred[wid * 2 + 1] = lsum[1];
        }
        if (lane < 4) {
            #pragma unroll
            for (int g = 0; g < 2; ++g)
                #pragma unroll
                for (int o = 0; o < 4; ++o)
                    wred[wid * 32 + g * 16 + oq * 4 + o] = acc[g][o];
        }
        __syncthreads();
        if (tid < 32) {
            const int g2 = tid & 1, o2 = tid >> 1;
            float Z = 0.f, sv = 0.f;
            #pragma unroll
            for (int wi = 0; wi < NWARPS; ++wi) {
                Z  += sred[wi * 2 + g2];
                sv += wred[wi * 32 + g2 * 16 + o2];
            }
            sv /= Z;
            float sq = sv * sv;
            #pragma unroll
            for (int off = 2; off <= 16; off <<= 1)
                sq += __shfl_xor_sync(0xffffffffu, sq, off);
            const float coef = sq / (1.f + sq) * rsqrtf(sq);
            outv[g2 * 16 + o2] = sv * coef;
        }
        __syncthreads();
    }

    // ================= output: [C, B, 1, 1, 16] =================
    if (tid < 32) {
        const int g2 = tid & 1, o2 = tid >> 1;
        out[((size_t)c * Bb + bbase + g2) * 16 + o2] = outv[g2 * 16 + o2];
    }
}

// ---------------- host ----------------
typedef CUresult (*EncodeTiledFn)(
    CUtensorMap*, CUtensorMapDataType, cuuint32_t, void*,
    const cuuint64_t*, const cuuint64_t*, const cuuint32_t*, const cuuint32_t*,
    CUtensorMapInterleave, CUtensorMapSwizzle, CUtensorMapL2promotion,
    CUtensorMapFloatOOBfill);

extern "C" void kernel_launch(void* const* d_in, const int* in_sizes, int n_in,
                              void* d_out, int out_size)
{
    const float* x = (const float*)d_in[0];
    void* w = (void*)d_in[1];
    float* out = (float*)d_out;

    EncodeTiledFn encode = nullptr;
    cudaDriverEntryPointQueryResult qr;
    cudaGetDriverEntryPoint("cuTensorMapEncodeTiled", (void**)&encode,
                            cudaEnableDefault, &qr);

    CUtensorMap tmap;
    cuuint64_t dims[2]    = { 128, (cuuint64_t)Cc * Nn };
    cuuint64_t strides[1] = { 128 * 4 };
    cuuint32_t box[2]     = { 32, RPB };
    cuuint32_t estr[2]    = { 1, 1 };
    encode(&tmap, CU_TENSOR_MAP_DATA_TYPE_FLOAT32, 2, w,
           dims, strides, box, estr,
           CU_TENSOR_MAP_INTERLEAVE_NONE, CU_TENSOR_MAP_SWIZZLE_128B,
           CU_TENSOR_MAP_L2_PROMOTION_L2_128B,
           CU_TENSOR_MAP_FLOAT_OOB_FILL_NONE);

    cudaFuncSetAttribute(capsule_kernel,
                         cudaFuncAttributeMaxDynamicSharedMemorySize, SMEM_BYTES);

    const int grid = Cc * (Bb / 2);   // 1280 CTAs
    capsule_kernel<<<grid, NTHREADS, SMEM_BYTES>>>(tmap, x, out);
}